// round 15
// baseline (speedup 1.0000x reference)
#include <cuda_runtime.h>
#include <cuda_fp16.h>

#define D      128
#define NMAX   50000
#define EMAX   600000

// Scratch (device globals: allocation-free per harness rules)
__device__ __half g_hh[NMAX * D];    // h_scaled = (x @ W) * dinv[row], fp16
__device__ __half g_xh[NMAX * D];    // layer output ping buffer, fp16
__device__ float  g_dinv[NMAX];
__device__ int    g_cnt[NMAX];
__device__ int    g_off[NMAX];
__device__ int    g_end[NMAX];
__device__ int    g_cur[NMAX];
__device__ int    g_total;
__device__ int    g_col[EMAX];       // CSR (by dst) column = src ids
__device__ int    g_is64;            // edge_index dtype flag (1 = int64)
__device__ __half g_Wht[3][D * D];   // W^T fp16  [layer][n][k]

__device__ __forceinline__ int load_idx(const void* buf, int i) {
    if (g_is64) return (int)((const long long*)buf)[i];
    return ((const int*)buf)[i];
}

// ---------------------------------------------------------------- init: zero cnt + dtype probe
__global__ void init_kernel(const int* __restrict__ w, int N) {
    int i = blockIdx.x * 256 + threadIdx.x;
    if (i < N) g_cnt[i] = 0;
    if (blockIdx.x == 0) {
        int bad = (w[2 * threadIdx.x + 1] != 0) ? 1 : 0;  // 256 odd words
        int any = __syncthreads_or(bad);
        if (threadIdx.x == 0) { g_is64 = !any; g_total = 0; }
    }
}

// ---------------------------------------------------------------- CSR build
__global__ void count_kernel(const void* __restrict__ ei, int E) {
    int e = blockIdx.x * blockDim.x + threadIdx.x;
    if (e < E) atomicAdd(&g_cnt[load_idx(ei, E + e)], 1);
}

// Unordered offset assignment: each node grabs a private contiguous range.
__global__ void offsets_kernel(int N) {
    int i = blockIdx.x * 256 + threadIdx.x;
    if (i >= N) return;
    int c = g_cnt[i];
    int off = atomicAdd(&g_total, c);
    g_off[i] = off;
    g_end[i] = off + c;
    g_cur[i] = off;
    g_dinv[i] = rsqrtf((float)(c + 1));       // +1 self-loop
}

__global__ void fill_kernel(const void* __restrict__ ei, int E) {
    int e = blockIdx.x * blockDim.x + threadIdx.x;
    if (e < E) {
        int dst = load_idx(ei, E + e);
        int src = load_idx(ei, e);
        int p = atomicAdd(&g_cur[dst], 1);
        g_col[p] = src;
    }
}

// ---------------------------------------------------------------- W convert (all 3 layers)
// W [k][n] fp32 -> W^T [n][k] fp16.
__global__ void wsplit_kernel(const float* __restrict__ W1,
                              const float* __restrict__ W2,
                              const float* __restrict__ W3) {
    int idx = blockIdx.x * blockDim.x + threadIdx.x;
    if (idx >= 3 * D * D) return;
    int l = idx >> 14;
    int r = idx & (D * D - 1);
    const float* W = (l == 0) ? W1 : (l == 1) ? W2 : W3;
    int k = r >> 7, n = r & 127;
    g_Wht[l][n * D + k] = __float2half(W[r]);
}

// ---------------------------------------------------------------- Tensor GEMM
// H[m][n] = fp16( dinv[m] * sum_k relu?(X[m][k]) * W[k][n] )
// Block tile 64(M) x 128(N), full K=128 in smem. 256 thr = 8 warps.
// MODE 0: X fp32 (layer 1) -> A split fp16 hi/lo: AhW + AlW (2 terms)
// MODE 1: X fp16 exact     -> AW (1 term)
#define APAD   8
#define AROW   (D + APAD)                 // 136 fp16 per padded row
#define SM_AH  0
#define SM_AL  (64 * AROW * 2)
#define SM_WH  (2 * 64 * AROW * 2)
#define SM_TOT (SM_WH + D * AROW * 2)     // 69632 bytes

__device__ __forceinline__ void mma_f16(
    float& c0, float& c1, float& c2, float& c3,
    unsigned a0, unsigned a1, unsigned a2, unsigned a3,
    unsigned b0, unsigned b1)
{
    asm volatile(
        "mma.sync.aligned.m16n8k16.row.col.f32.f16.f16.f32 "
        "{%0,%1,%2,%3}, {%4,%5,%6,%7}, {%8,%9}, {%0,%1,%2,%3};\n"
        : "+f"(c0), "+f"(c1), "+f"(c2), "+f"(c3)
        : "r"(a0), "r"(a1), "r"(a2), "r"(a3), "r"(b0), "r"(b1));
}

template<int MODE>
__global__ void __launch_bounds__(256) gemm_tc_kernel(
    const void* __restrict__ Xin, int N, int apply_relu, int layer)
{
    extern __shared__ char smem[];
    __half* As_h = (__half*)(smem + SM_AH);
    __half* As_l = (__half*)(smem + SM_AL);
    __half* Ws_h = (__half*)(smem + SM_WH);

    int tid = threadIdx.x;
    int m0  = blockIdx.x * 64;

    // ---- load W^T into padded smem: 128 rows x 256B
    {
        const uint4* gh = (const uint4*)g_Wht[layer];
        #pragma unroll
        for (int r = 0; r < 8; r++) {
            int idx = tid + r * 256;
            int row = idx >> 4, ch = idx & 15;
            ((uint4*)((char*)Ws_h + row * AROW * 2))[ch] = gh[row * 16 + ch];
        }
    }

    // ---- load A tile
    if (MODE == 0) {
        const float* X = (const float*)Xin;
        #pragma unroll
        for (int r = 0; r < 8; r++) {
            int idx = tid + r * 256;
            int row = idx >> 5, c4 = idx & 31;
            int gm = m0 + row;
            float4 v = make_float4(0.f, 0.f, 0.f, 0.f);
            if (gm < N) v = *(const float4*)(X + (size_t)gm * D + c4 * 4);
            if (apply_relu) {
                v.x = fmaxf(v.x, 0.f); v.y = fmaxf(v.y, 0.f);
                v.z = fmaxf(v.z, 0.f); v.w = fmaxf(v.w, 0.f);
            }
            __half h0 = __float2half(v.x), h1 = __float2half(v.y);
            __half h2 = __float2half(v.z), h3 = __float2half(v.w);
            __half l0 = __float2half(v.x - __half2float(h0));
            __half l1 = __float2half(v.y - __half2float(h1));
            __half l2 = __float2half(v.z - __half2float(h2));
            __half l3 = __float2half(v.w - __half2float(h3));
            __half2* ph = (__half2*)(As_h + row * AROW + c4 * 4);
            __half2* pl = (__half2*)(As_l + row * AROW + c4 * 4);
            ph[0] = __half2(h0, h1); ph[1] = __half2(h2, h3);
            pl[0] = __half2(l0, l1); pl[1] = __half2(l2, l3);
        }
    } else {
        // fp16 input: 64 rows x 256B
        const uint4* X = (const uint4*)Xin;     // 16 uint4 per row
        const __half2 z2 = __half2(__half(0.f), __half(0.f));
        #pragma unroll
        for (int r = 0; r < 4; r++) {
            int idx = tid + r * 256;            // 1024 uint4 slots
            int row = idx >> 4, ch = idx & 15;
            int gm = m0 + row;
            uint4 v = make_uint4(0u, 0u, 0u, 0u);
            if (gm < N) v = X[(size_t)gm * 16 + ch];
            if (apply_relu) {
                __half2* h = (__half2*)&v;
                h[0] = __hmax2(h[0], z2); h[1] = __hmax2(h[1], z2);
                h[2] = __hmax2(h[2], z2); h[3] = __hmax2(h[3], z2);
            }
            *(uint4*)(As_h + row * AROW + ch * 8) = v;
        }
    }
    __syncthreads();

    int wid  = tid >> 5, lane = tid & 31;
    int wm   = wid & 1, wn = wid >> 1;
    int g    = lane >> 2;
    int kk   = (lane & 3) * 2;

    float acc[2][4][4];
    #pragma unroll
    for (int mt = 0; mt < 2; mt++)
        #pragma unroll
        for (int nt = 0; nt < 4; nt++)
            #pragma unroll
            for (int r = 0; r < 4; r++) acc[mt][nt][r] = 0.f;

    #pragma unroll
    for (int ks = 0; ks < 8; ks++) {
        int k0 = ks * 16;
        unsigned ah[2][4], al[2][4];
        #pragma unroll
        for (int mt = 0; mt < 2; mt++) {
            int r0 = wm * 32 + mt * 16 + g;
            ah[mt][0] = *(const unsigned*)(As_h + r0 * AROW + k0 + kk);
            ah[mt][1] = *(const unsigned*)(As_h + (r0 + 8) * AROW + k0 + kk);
            ah[mt][2] = *(const unsigned*)(As_h + r0 * AROW + k0 + kk + 8);
            ah[mt][3] = *(const unsigned*)(As_h + (r0 + 8) * AROW + k0 + kk + 8);
            if (MODE == 0) {
                al[mt][0] = *(const unsigned*)(As_l + r0 * AROW + k0 + kk);
                al[mt][1] = *(const unsigned*)(As_l + (r0 + 8) * AROW + k0 + kk);
                al[mt][2] = *(const unsigned*)(As_l + r0 * AROW + k0 + kk + 8);
                al[mt][3] = *(const unsigned*)(As_l + (r0 + 8) * AROW + k0 + kk + 8);
            }
        }
        #pragma unroll
        for (int nt = 0; nt < 4; nt++) {
            int c = wn * 32 + nt * 8 + g;
            unsigned bh0 = *(const unsigned*)(Ws_h + c * AROW + k0 + kk);
            unsigned bh1 = *(const unsigned*)(Ws_h + c * AROW + k0 + kk + 8);
            #pragma unroll
            for (int mt = 0; mt < 2; mt++) {
                float* a = acc[mt][nt];
                mma_f16(a[0], a[1], a[2], a[3],
                        ah[mt][0], ah[mt][1], ah[mt][2], ah[mt][3], bh0, bh1);
                if (MODE == 0)
                    mma_f16(a[0], a[1], a[2], a[3],
                            al[mt][0], al[mt][1], al[mt][2], al[mt][3], bh0, bh1);
            }
        }
    }

    // ---- epilogue: scale by dinv[row], store fp16
    #pragma unroll
    for (int mt = 0; mt < 2; mt++) {
        int r0 = m0 + wm * 32 + mt * 16 + g;
        int r1 = r0 + 8;
        float dv0 = (r0 < N) ? g_dinv[r0] : 0.f;
        float dv1 = (r1 < N) ? g_dinv[r1] : 0.f;
        #pragma unroll
        for (int nt = 0; nt < 4; nt++) {
            int col = wn * 32 + nt * 8 + (lane & 3) * 2;
            float* a = acc[mt][nt];
            if (r0 < N)
                *(__half2*)(g_hh + (size_t)r0 * D + col) =
                    __floats2half2_rn(a[0] * dv0, a[1] * dv0);
            if (r1 < N)
                *(__half2*)(g_hh + (size_t)r1 * D + col) =
                    __floats2half2_rn(a[2] * dv1, a[3] * dv1);
        }
    }
}

// ---------------------------------------------------------------- Aggregate
// out[i] = dinv[i] * (h_s[i] + sum_{e in row i} h_s[col[e]]) + b
// one warp per node, GRID-STRIDE over nodes (no wave transitions).
__device__ __forceinline__ void add_h4(float4& acc, uint2 v) {
    float2 a = __half22float2(*(__half2*)&v.x);
    float2 b = __half22float2(*(__half2*)&v.y);
    acc.x += a.x; acc.y += a.y; acc.z += b.x; acc.w += b.y;
}

#define AGG_BLOCKS 592   // 4 blocks/SM x 148 SMs; 8 warps each

template<typename OutT>
__global__ void __launch_bounds__(256) agg_kernel(
    const float* __restrict__ bias, OutT* __restrict__ out, int N,
    int zero_first)
{
    int warp0 = (int)((blockIdx.x * blockDim.x + threadIdx.x) >> 5);
    int lane  = threadIdx.x & 31;
    const int nwarps = AGG_BLOCKS * 8;
    const uint2* H2 = (const uint2*)g_hh;   // 32 uint2 per row
    float4 bb = ((const float4*)bias)[lane];

    for (int w = warp0; w < N; w += nwarps) {
        if (zero_first && w == 0) {   // final layer: out[0] = zeros
            if (sizeof(OutT) == 4)
                ((float4*)out)[lane] = make_float4(0.f, 0.f, 0.f, 0.f);
            else
                ((uint2*)out)[lane] = make_uint2(0u, 0u);
            continue;
        }

        float4 acc = make_float4(0.f, 0.f, 0.f, 0.f);
        add_h4(acc, H2[(size_t)w * 32 + lane]); // self-loop term
        int beg = g_off[w], end = g_end[w];

        int e = beg;
        for (; e + 3 < end; e += 4) {
            int s0 = g_col[e],     s1 = g_col[e + 1];
            int s2 = g_col[e + 2], s3 = g_col[e + 3];
            uint2 v0 = H2[(size_t)s0 * 32 + lane];
            uint2 v1 = H2[(size_t)s1 * 32 + lane];
            uint2 v2 = H2[(size_t)s2 * 32 + lane];
            uint2 v3 = H2[(size_t)s3 * 32 + lane];
            add_h4(acc, v0); add_h4(acc, v1);
            add_h4(acc, v2); add_h4(acc, v3);
        }
        for (; e < end; e++) {
            uint2 v0 = H2[(size_t)g_col[e] * 32 + lane];
            add_h4(acc, v0);
        }

        float dv = g_dinv[w];
        float4 o;
        o.x = fmaf(acc.x, dv, bb.x);
        o.y = fmaf(acc.y, dv, bb.y);
        o.z = fmaf(acc.z, dv, bb.z);
        o.w = fmaf(acc.w, dv, bb.w);
        if (sizeof(OutT) == 4) {
            ((float4*)out)[(size_t)w * 32 + lane] = o;
        } else {
            uint2 p;
            *(__half2*)&p.x = __floats2half2_rn(o.x, o.y);
            *(__half2*)&p.y = __floats2half2_rn(o.z, o.w);
            ((uint2*)out)[(size_t)w * 32 + lane] = p;
        }
    }
}

// ---------------------------------------------------------------- launch
// Single stream — gemm1 reads g_dinv, so it MUST follow offsets_kernel.
extern "C" void kernel_launch(void* const* d_in, const int* in_sizes, int n_in,
                              void* d_out, int out_size)
{
    const float* emb = (const float*)d_in[0];
    const float* W1  = (const float*)d_in[1];
    const float* b1  = (const float*)d_in[2];
    const float* W2  = (const float*)d_in[3];
    const float* b2  = (const float*)d_in[4];
    const float* W3  = (const float*)d_in[5];
    const float* b3  = (const float*)d_in[6];
    const void*  ei  = d_in[7];

    int N = in_sizes[0] / D;
    int E = in_sizes[7] / 2;
    float* out = (float*)d_out;

    void* p;
    cudaGetSymbolAddress(&p, g_xh);  __half* Xh = (__half*)p;

    static int smem_set = 0;
    if (!smem_set) {
        cudaFuncSetAttribute(gemm_tc_kernel<0>,
            cudaFuncAttributeMaxDynamicSharedMemorySize, SM_TOT);
        cudaFuncSetAttribute(gemm_tc_kernel<1>,
            cudaFuncAttributeMaxDynamicSharedMemorySize, SM_TOT);
        smem_set = 1;
    }

    int tb = 256;
    int nblk = (N + 255) / 256;
    int gemm_grid = (N + 63) / 64;

    init_kernel<<<nblk, 256>>>((const int*)ei, N);
    count_kernel<<<(E + tb - 1) / tb, tb>>>(ei, E);
    offsets_kernel<<<nblk, 256>>>(N);
    fill_kernel<<<(E + tb - 1) / tb, tb>>>(ei, E);
    wsplit_kernel<<<(3 * D * D + tb - 1) / tb, tb>>>(W1, W2, W3);

    // layer 1 (fp32 input, 2-term A-split; dinv in epilogue — after offsets)
    gemm_tc_kernel<0><<<gemm_grid, 256, SM_TOT>>>(emb, N, 0, 0);
    agg_kernel<__half><<<AGG_BLOCKS, 256>>>(b1, Xh, N, 0);
    // layer 2 (fp16 input exact, 1-term; relu fused)
    gemm_tc_kernel<1><<<gemm_grid, 256, SM_TOT>>>(Xh, N, 1, 1);
    agg_kernel<__half><<<AGG_BLOCKS, 256>>>(b2, Xh, N, 0);
    // layer 3
    gemm_tc_kernel<1><<<gemm_grid, 256, SM_TOT>>>(Xh, N, 1, 2);
    agg_kernel<float><<<AGG_BLOCKS, 256>>>(b3, out, N, 1);
}

// round 16
// speedup vs baseline: 1.2547x; 1.2547x over previous
#include <cuda_runtime.h>
#include <cuda_fp16.h>

#define D      128
#define NMAX   50000
#define EMAX   600000

// Scratch (device globals: allocation-free per harness rules)
__device__ __half g_hh[NMAX * D];    // h_scaled = (x @ W) * dinv[row], fp16
__device__ __half g_xh[NMAX * D];    // layer output ping buffer, fp16
__device__ float  g_dinv[NMAX];
__device__ int    g_cnt[NMAX];
__device__ int    g_off[NMAX];
__device__ int    g_end[NMAX];
__device__ int    g_cur[NMAX];
__device__ int    g_total;
__device__ int    g_col[EMAX];       // CSR (by dst) column = src ids
__device__ int    g_is64;            // edge_index dtype flag (1 = int64)
__device__ __half g_Wht[3][D * D];   // W^T fp16  [layer][n][k]

__device__ __forceinline__ int load_idx(const void* buf, int i) {
    if (g_is64) return (int)((const long long*)buf)[i];
    return ((const int*)buf)[i];
}

// ---------------------------------------------------------------- init: zero cnt + dtype probe
__global__ void init_kernel(const int* __restrict__ w, int N) {
    int i = blockIdx.x * 256 + threadIdx.x;
    if (i < N) g_cnt[i] = 0;
    if (blockIdx.x == 0) {
        int bad = (w[2 * threadIdx.x + 1] != 0) ? 1 : 0;  // 256 odd words
        int any = __syncthreads_or(bad);
        if (threadIdx.x == 0) { g_is64 = !any; g_total = 0; }
    }
}

// ---------------------------------------------------------------- CSR build
__global__ void count_kernel(const void* __restrict__ ei, int E) {
    int e = blockIdx.x * blockDim.x + threadIdx.x;
    if (e < E) atomicAdd(&g_cnt[load_idx(ei, E + e)], 1);
}

// Unordered offset assignment: each node grabs a private contiguous range.
__global__ void offsets_kernel(int N) {
    int i = blockIdx.x * 256 + threadIdx.x;
    if (i >= N) return;
    int c = g_cnt[i];
    int off = atomicAdd(&g_total, c);
    g_off[i] = off;
    g_end[i] = off + c;
    g_cur[i] = off;
    g_dinv[i] = rsqrtf((float)(c + 1));       // +1 self-loop
}

__global__ void fill_kernel(const void* __restrict__ ei, int E) {
    int e = blockIdx.x * blockDim.x + threadIdx.x;
    if (e < E) {
        int dst = load_idx(ei, E + e);
        int src = load_idx(ei, e);
        int p = atomicAdd(&g_cur[dst], 1);
        g_col[p] = src;
    }
}

// ---------------------------------------------------------------- W convert (all 3 layers)
// W [k][n] fp32 -> W^T [n][k] fp16.
__global__ void wsplit_kernel(const float* __restrict__ W1,
                              const float* __restrict__ W2,
                              const float* __restrict__ W3) {
    int idx = blockIdx.x * blockDim.x + threadIdx.x;
    if (idx >= 3 * D * D) return;
    int l = idx >> 14;
    int r = idx & (D * D - 1);
    const float* W = (l == 0) ? W1 : (l == 1) ? W2 : W3;
    int k = r >> 7, n = r & 127;
    g_Wht[l][n * D + k] = __float2half(W[r]);
}

// ---------------------------------------------------------------- Tensor GEMM
// H[m][n] = fp16( dinv[m] * sum_k relu?(X[m][k]) * W[k][n] )
// Block tile 64(M) x 128(N), full K=128 in smem. 256 thr = 8 warps.
// MODE 0: X fp32 (layer 1) -> A split fp16 hi/lo: AhW + AlW (2 terms)
// MODE 1: X fp16 exact     -> AW (1 term); As_l unused (launch w/ smaller smem)
#define APAD   8
#define AROW   (D + APAD)                 // 136 fp16 per padded row
#define SM_AH   0
#define SM_AL   (64 * AROW * 2)
#define SM_WH0  (2 * 64 * AROW * 2)       // MODE 0: W after Ah+Al
#define SM_WH1  (64 * AROW * 2)           // MODE 1: W right after Ah
#define SM_TOT0 (SM_WH0 + D * AROW * 2)   // 69632 bytes
#define SM_TOT1 (SM_WH1 + D * AROW * 2)   // 52224 bytes

__device__ __forceinline__ void mma_f16(
    float& c0, float& c1, float& c2, float& c3,
    unsigned a0, unsigned a1, unsigned a2, unsigned a3,
    unsigned b0, unsigned b1)
{
    asm volatile(
        "mma.sync.aligned.m16n8k16.row.col.f32.f16.f16.f32 "
        "{%0,%1,%2,%3}, {%4,%5,%6,%7}, {%8,%9}, {%0,%1,%2,%3};\n"
        : "+f"(c0), "+f"(c1), "+f"(c2), "+f"(c3)
        : "r"(a0), "r"(a1), "r"(a2), "r"(a3), "r"(b0), "r"(b1));
}

template<int MODE>
__global__ void __launch_bounds__(256) gemm_tc_kernel(
    const void* __restrict__ Xin, int N, int apply_relu, int layer)
{
    extern __shared__ char smem[];
    __half* As_h = (__half*)(smem + SM_AH);
    __half* As_l = (__half*)(smem + SM_AL);          // MODE 0 only
    __half* Ws_h = (__half*)(smem + (MODE == 0 ? SM_WH0 : SM_WH1));

    int tid = threadIdx.x;
    int m0  = blockIdx.x * 64;

    // ---- load W^T into padded smem: 128 rows x 256B
    {
        const uint4* gh = (const uint4*)g_Wht[layer];
        #pragma unroll
        for (int r = 0; r < 8; r++) {
            int idx = tid + r * 256;
            int row = idx >> 4, ch = idx & 15;
            ((uint4*)((char*)Ws_h + row * AROW * 2))[ch] = gh[row * 16 + ch];
        }
    }

    // ---- load A tile
    if (MODE == 0) {
        const float* X = (const float*)Xin;
        #pragma unroll
        for (int r = 0; r < 8; r++) {
            int idx = tid + r * 256;
            int row = idx >> 5, c4 = idx & 31;
            int gm = m0 + row;
            float4 v = make_float4(0.f, 0.f, 0.f, 0.f);
            if (gm < N) v = *(const float4*)(X + (size_t)gm * D + c4 * 4);
            if (apply_relu) {
                v.x = fmaxf(v.x, 0.f); v.y = fmaxf(v.y, 0.f);
                v.z = fmaxf(v.z, 0.f); v.w = fmaxf(v.w, 0.f);
            }
            __half h0 = __float2half(v.x), h1 = __float2half(v.y);
            __half h2 = __float2half(v.z), h3 = __float2half(v.w);
            __half l0 = __float2half(v.x - __half2float(h0));
            __half l1 = __float2half(v.y - __half2float(h1));
            __half l2 = __float2half(v.z - __half2float(h2));
            __half l3 = __float2half(v.w - __half2float(h3));
            __half2* ph = (__half2*)(As_h + row * AROW + c4 * 4);
            __half2* pl = (__half2*)(As_l + row * AROW + c4 * 4);
            ph[0] = __half2(h0, h1); ph[1] = __half2(h2, h3);
            pl[0] = __half2(l0, l1); pl[1] = __half2(l2, l3);
        }
    } else {
        // fp16 input: 64 rows x 256B
        const uint4* X = (const uint4*)Xin;     // 16 uint4 per row
        const __half2 z2 = __half2(__half(0.f), __half(0.f));
        #pragma unroll
        for (int r = 0; r < 4; r++) {
            int idx = tid + r * 256;            // 1024 uint4 slots
            int row = idx >> 4, ch = idx & 15;
            int gm = m0 + row;
            uint4 v = make_uint4(0u, 0u, 0u, 0u);
            if (gm < N) v = X[(size_t)gm * 16 + ch];
            if (apply_relu) {
                __half2* h = (__half2*)&v;
                h[0] = __hmax2(h[0], z2); h[1] = __hmax2(h[1], z2);
                h[2] = __hmax2(h[2], z2); h[3] = __hmax2(h[3], z2);
            }
            *(uint4*)(As_h + row * AROW + ch * 8) = v;
        }
    }
    __syncthreads();

    int wid  = tid >> 5, lane = tid & 31;
    int wm   = wid & 1, wn = wid >> 1;
    int g    = lane >> 2;
    int kk   = (lane & 3) * 2;

    float acc[2][4][4];
    #pragma unroll
    for (int mt = 0; mt < 2; mt++)
        #pragma unroll
        for (int nt = 0; nt < 4; nt++)
            #pragma unroll
            for (int r = 0; r < 4; r++) acc[mt][nt][r] = 0.f;

    #pragma unroll
    for (int ks = 0; ks < 8; ks++) {
        int k0 = ks * 16;
        unsigned ah[2][4], al[2][4];
        #pragma unroll
        for (int mt = 0; mt < 2; mt++) {
            int r0 = wm * 32 + mt * 16 + g;
            ah[mt][0] = *(const unsigned*)(As_h + r0 * AROW + k0 + kk);
            ah[mt][1] = *(const unsigned*)(As_h + (r0 + 8) * AROW + k0 + kk);
            ah[mt][2] = *(const unsigned*)(As_h + r0 * AROW + k0 + kk + 8);
            ah[mt][3] = *(const unsigned*)(As_h + (r0 + 8) * AROW + k0 + kk + 8);
            if (MODE == 0) {
                al[mt][0] = *(const unsigned*)(As_l + r0 * AROW + k0 + kk);
                al[mt][1] = *(const unsigned*)(As_l + (r0 + 8) * AROW + k0 + kk);
                al[mt][2] = *(const unsigned*)(As_l + r0 * AROW + k0 + kk + 8);
                al[mt][3] = *(const unsigned*)(As_l + (r0 + 8) * AROW + k0 + kk + 8);
            }
        }
        #pragma unroll
        for (int nt = 0; nt < 4; nt++) {
            int c = wn * 32 + nt * 8 + g;
            unsigned bh0 = *(const unsigned*)(Ws_h + c * AROW + k0 + kk);
            unsigned bh1 = *(const unsigned*)(Ws_h + c * AROW + k0 + kk + 8);
            #pragma unroll
            for (int mt = 0; mt < 2; mt++) {
                float* a = acc[mt][nt];
                mma_f16(a[0], a[1], a[2], a[3],
                        ah[mt][0], ah[mt][1], ah[mt][2], ah[mt][3], bh0, bh1);
                if (MODE == 0)
                    mma_f16(a[0], a[1], a[2], a[3],
                            al[mt][0], al[mt][1], al[mt][2], al[mt][3], bh0, bh1);
            }
        }
    }

    // ---- epilogue: scale by dinv[row], store fp16
    #pragma unroll
    for (int mt = 0; mt < 2; mt++) {
        int r0 = m0 + wm * 32 + mt * 16 + g;
        int r1 = r0 + 8;
        float dv0 = (r0 < N) ? g_dinv[r0] : 0.f;
        float dv1 = (r1 < N) ? g_dinv[r1] : 0.f;
        #pragma unroll
        for (int nt = 0; nt < 4; nt++) {
            int col = wn * 32 + nt * 8 + (lane & 3) * 2;
            float* a = acc[mt][nt];
            if (r0 < N)
                *(__half2*)(g_hh + (size_t)r0 * D + col) =
                    __floats2half2_rn(a[0] * dv0, a[1] * dv0);
            if (r1 < N)
                *(__half2*)(g_hh + (size_t)r1 * D + col) =
                    __floats2half2_rn(a[2] * dv1, a[3] * dv1);
        }
    }
}

// ---------------------------------------------------------------- Aggregate
// out[i] = dinv[i] * (h_s[i] + sum_{e in row i} h_s[col[e]]) + b
// one warp per node (proven best); lane handles 4 halves (8B) of the row.
__device__ __forceinline__ void add_h4(float4& acc, uint2 v) {
    float2 a = __half22float2(*(__half2*)&v.x);
    float2 b = __half22float2(*(__half2*)&v.y);
    acc.x += a.x; acc.y += a.y; acc.z += b.x; acc.w += b.y;
}

template<typename OutT>
__global__ void __launch_bounds__(256) agg_kernel(
    const float* __restrict__ bias, OutT* __restrict__ out, int N,
    int zero_first)
{
    int w    = (int)((blockIdx.x * blockDim.x + threadIdx.x) >> 5);
    int lane = threadIdx.x & 31;
    if (w >= N) return;

    if (zero_first && w == 0) {   // final layer: out[0] = zeros
        if (sizeof(OutT) == 4)
            ((float4*)out)[lane] = make_float4(0.f, 0.f, 0.f, 0.f);
        else
            ((uint2*)out)[lane] = make_uint2(0u, 0u);
        return;
    }

    const uint2* H2 = (const uint2*)g_hh;   // 32 uint2 per row
    float4 acc = make_float4(0.f, 0.f, 0.f, 0.f);
    add_h4(acc, H2[(size_t)w * 32 + lane]); // self-loop term
    int beg = g_off[w], end = g_end[w];

    int e = beg;
    for (; e + 3 < end; e += 4) {
        int s0 = g_col[e],     s1 = g_col[e + 1];
        int s2 = g_col[e + 2], s3 = g_col[e + 3];
        uint2 v0 = H2[(size_t)s0 * 32 + lane];
        uint2 v1 = H2[(size_t)s1 * 32 + lane];
        uint2 v2 = H2[(size_t)s2 * 32 + lane];
        uint2 v3 = H2[(size_t)s3 * 32 + lane];
        add_h4(acc, v0); add_h4(acc, v1);
        add_h4(acc, v2); add_h4(acc, v3);
    }
    for (; e < end; e++) {
        uint2 v0 = H2[(size_t)g_col[e] * 32 + lane];
        add_h4(acc, v0);
    }

    float dv = g_dinv[w];
    float4 bb = ((const float4*)bias)[lane];
    float4 o;
    o.x = fmaf(acc.x, dv, bb.x);
    o.y = fmaf(acc.y, dv, bb.y);
    o.z = fmaf(acc.z, dv, bb.z);
    o.w = fmaf(acc.w, dv, bb.w);
    if (sizeof(OutT) == 4) {
        ((float4*)out)[(size_t)w * 32 + lane] = o;
    } else {
        uint2 p;
        *(__half2*)&p.x = __floats2half2_rn(o.x, o.y);
        *(__half2*)&p.y = __floats2half2_rn(o.z, o.w);
        ((uint2*)out)[(size_t)w * 32 + lane] = p;
    }
}

// ---------------------------------------------------------------- launch
// Fork AFTER offsets: s2 runs {wsplit, gemm1} (needs g_dinv + W only),
// default runs fill (needs g_cur/g_off only). agg1 joins both. No races.
extern "C" void kernel_launch(void* const* d_in, const int* in_sizes, int n_in,
                              void* d_out, int out_size)
{
    const float* emb = (const float*)d_in[0];
    const float* W1  = (const float*)d_in[1];
    const float* b1  = (const float*)d_in[2];
    const float* W2  = (const float*)d_in[3];
    const float* b2  = (const float*)d_in[4];
    const float* W3  = (const float*)d_in[5];
    const float* b3  = (const float*)d_in[6];
    const void*  ei  = d_in[7];

    int N = in_sizes[0] / D;
    int E = in_sizes[7] / 2;
    float* out = (float*)d_out;

    void* p;
    cudaGetSymbolAddress(&p, g_xh);  __half* Xh = (__half*)p;

    static cudaStream_t s2 = nullptr;
    static cudaEvent_t evOff = nullptr, evJoin = nullptr;
    if (!s2) {
        cudaFuncSetAttribute(gemm_tc_kernel<0>,
            cudaFuncAttributeMaxDynamicSharedMemorySize, SM_TOT0);
        cudaFuncSetAttribute(gemm_tc_kernel<1>,
            cudaFuncAttributeMaxDynamicSharedMemorySize, SM_TOT1);
        cudaStreamCreateWithFlags(&s2, cudaStreamNonBlocking);
        cudaEventCreateWithFlags(&evOff, cudaEventDisableTiming);
        cudaEventCreateWithFlags(&evJoin, cudaEventDisableTiming);
    }

    int tb = 256;
    int nblk = (N + 255) / 256;
    int gemm_grid = (N + 63) / 64;
    int agg_grid  = (N + 7) / 8;

    // ---- serial prefix: init -> count -> offsets (produces g_dinv)
    init_kernel<<<nblk, 256>>>((const int*)ei, N);
    count_kernel<<<(E + tb - 1) / tb, tb>>>(ei, E);
    offsets_kernel<<<nblk, 256>>>(N);
    cudaEventRecord(evOff, 0);

    // ---- fork: s2 does wsplit + layer-1 GEMM (reads g_dinv, W; not g_col)
    cudaStreamWaitEvent(s2, evOff, 0);
    wsplit_kernel<<<(3 * D * D + tb - 1) / tb, tb, 0, s2>>>(W1, W2, W3);
    gemm_tc_kernel<0><<<gemm_grid, 256, SM_TOT0, s2>>>(emb, N, 0, 0);
    cudaEventRecord(evJoin, s2);

    // ---- default: fill CSR columns (concurrent with s2)
    fill_kernel<<<(E + tb - 1) / tb, tb>>>(ei, E);

    // ---- join, then the dependent chain
    cudaStreamWaitEvent(0, evJoin, 0);
    agg_kernel<__half><<<agg_grid, 256>>>(b1, Xh, N, 0);
    gemm_tc_kernel<1><<<gemm_grid, 256, SM_TOT1>>>(Xh, N, 1, 1);
    agg_kernel<__half><<<agg_grid, 256>>>(b2, Xh, N, 0);
    gemm_tc_kernel<1><<<gemm_grid, 256, SM_TOT1>>>(Xh, N, 1, 2);
    agg_kernel<float><<<agg_grid, 256>>>(b3, out, N, 1);
}

// round 17
// speedup vs baseline: 1.2987x; 1.0351x over previous
#include <cuda_runtime.h>
#include <cuda_fp16.h>

#define D      128
#define NMAX   50000
#define EMAX   600000

// Scratch (device globals: allocation-free per harness rules)
__device__ __half g_hh[NMAX * D];    // h_scaled = (x @ W) * dinv[row], fp16
__device__ __half g_xh[NMAX * D];    // layer output ping buffer, fp16
__device__ float  g_dinv[NMAX];
__device__ int    g_cnt[NMAX];
__device__ int    g_off[NMAX];
__device__ int    g_end[NMAX];
__device__ int    g_cur[NMAX];
__device__ int    g_total;
__device__ int    g_col[EMAX];       // CSR (by dst) column = src ids
__device__ int    g_is64;            // edge_index dtype flag (1 = int64)
__device__ __half g_Wht[3][D * D];   // W^T fp16  [layer][n][k]

__device__ __forceinline__ int load_idx(const void* buf, int i) {
    if (g_is64) return (int)((const long long*)buf)[i];
    return ((const int*)buf)[i];
}

// ---------------------------------------------------------------- init: zero cnt + dtype probe
__global__ void init_kernel(const int* __restrict__ w, int N) {
    int i = blockIdx.x * 256 + threadIdx.x;
    if (i < N) g_cnt[i] = 0;
    if (blockIdx.x == 0) {
        int bad = (w[2 * threadIdx.x + 1] != 0) ? 1 : 0;  // 256 odd words
        int any = __syncthreads_or(bad);
        if (threadIdx.x == 0) { g_is64 = !any; g_total = 0; }
    }
}

// ---------------------------------------------------------------- CSR build
__global__ void count_kernel(const void* __restrict__ ei, int E) {
    int e = blockIdx.x * blockDim.x + threadIdx.x;
    if (e < E) atomicAdd(&g_cnt[load_idx(ei, E + e)], 1);
}

// Unordered offset assignment: each node grabs a private contiguous range.
__global__ void offsets_kernel(int N) {
    int i = blockIdx.x * 256 + threadIdx.x;
    if (i >= N) return;
    int c = g_cnt[i];
    int off = atomicAdd(&g_total, c);
    g_off[i] = off;
    g_end[i] = off + c;
    g_cur[i] = off;
    g_dinv[i] = rsqrtf((float)(c + 1));       // +1 self-loop
}

__global__ void fill_kernel(const void* __restrict__ ei, int E) {
    int e = blockIdx.x * blockDim.x + threadIdx.x;
    if (e < E) {
        int dst = load_idx(ei, E + e);
        int src = load_idx(ei, e);
        int p = atomicAdd(&g_cur[dst], 1);
        g_col[p] = src;
    }
}

// ---------------------------------------------------------------- W convert (all 3 layers)
// W [k][n] fp32 -> W^T [n][k] fp16.  No dependencies — runs first on s2.
__global__ void wsplit_kernel(const float* __restrict__ W1,
                              const float* __restrict__ W2,
                              const float* __restrict__ W3) {
    int idx = blockIdx.x * blockDim.x + threadIdx.x;
    if (idx >= 3 * D * D) return;
    int l = idx >> 14;
    int r = idx & (D * D - 1);
    const float* W = (l == 0) ? W1 : (l == 1) ? W2 : W3;
    int k = r >> 7, n = r & 127;
    g_Wht[l][n * D + k] = __float2half(W[r]);
}

// ---------------------------------------------------------------- Tensor GEMM
// H[m][n] = fp16( dinv[m] * sum_k relu?(X[m][k]) * W[k][n] )
// Block tile 64(M) x 128(N), full K=128 in smem. 256 thr = 8 warps, 1 MMA term.
// MODE 0: X fp32 -> convert fp16 on load. MODE 1: X fp16.
#define APAD   8
#define AROW   (D + APAD)                 // 136 fp16 per padded row
#define SM_AH  0
#define SM_WH  (64 * AROW * 2)
#define SM_TOT (SM_WH + D * AROW * 2)     // 52224 bytes

__device__ __forceinline__ void mma_f16(
    float& c0, float& c1, float& c2, float& c3,
    unsigned a0, unsigned a1, unsigned a2, unsigned a3,
    unsigned b0, unsigned b1)
{
    asm volatile(
        "mma.sync.aligned.m16n8k16.row.col.f32.f16.f16.f32 "
        "{%0,%1,%2,%3}, {%4,%5,%6,%7}, {%8,%9}, {%0,%1,%2,%3};\n"
        : "+f"(c0), "+f"(c1), "+f"(c2), "+f"(c3)
        : "r"(a0), "r"(a1), "r"(a2), "r"(a3), "r"(b0), "r"(b1));
}

template<int MODE>
__global__ void __launch_bounds__(256) gemm_tc_kernel(
    const void* __restrict__ Xin, int N, int apply_relu, int layer)
{
    extern __shared__ char smem[];
    __half* As_h = (__half*)(smem + SM_AH);
    __half* Ws_h = (__half*)(smem + SM_WH);

    int tid = threadIdx.x;
    int m0  = blockIdx.x * 64;

    // ---- load W^T into padded smem: 128 rows x 256B
    {
        const uint4* gh = (const uint4*)g_Wht[layer];
        #pragma unroll
        for (int r = 0; r < 8; r++) {
            int idx = tid + r * 256;
            int row = idx >> 4, ch = idx & 15;
            ((uint4*)((char*)Ws_h + row * AROW * 2))[ch] = gh[row * 16 + ch];
        }
    }

    // ---- load A tile
    if (MODE == 0) {
        const float* X = (const float*)Xin;
        #pragma unroll
        for (int r = 0; r < 8; r++) {
            int idx = tid + r * 256;
            int row = idx >> 5, c4 = idx & 31;
            int gm = m0 + row;
            float4 v = make_float4(0.f, 0.f, 0.f, 0.f);
            if (gm < N) v = *(const float4*)(X + (size_t)gm * D + c4 * 4);
            if (apply_relu) {
                v.x = fmaxf(v.x, 0.f); v.y = fmaxf(v.y, 0.f);
                v.z = fmaxf(v.z, 0.f); v.w = fmaxf(v.w, 0.f);
            }
            __half2* ph = (__half2*)(As_h + row * AROW + c4 * 4);
            ph[0] = __floats2half2_rn(v.x, v.y);
            ph[1] = __floats2half2_rn(v.z, v.w);
        }
    } else {
        // fp16 input: 64 rows x 256B
        const uint4* X = (const uint4*)Xin;     // 16 uint4 per row
        const __half2 z2 = __half2(__half(0.f), __half(0.f));
        #pragma unroll
        for (int r = 0; r < 4; r++) {
            int idx = tid + r * 256;            // 1024 uint4 slots
            int row = idx >> 4, ch = idx & 15;
            int gm = m0 + row;
            uint4 v = make_uint4(0u, 0u, 0u, 0u);
            if (gm < N) v = X[(size_t)gm * 16 + ch];
            if (apply_relu) {
                __half2* h = (__half2*)&v;
                h[0] = __hmax2(h[0], z2); h[1] = __hmax2(h[1], z2);
                h[2] = __hmax2(h[2], z2); h[3] = __hmax2(h[3], z2);
            }
            *(uint4*)(As_h + row * AROW + ch * 8) = v;
        }
    }
    __syncthreads();

    int wid  = tid >> 5, lane = tid & 31;
    int wm   = wid & 1, wn = wid >> 1;
    int g    = lane >> 2;
    int kk   = (lane & 3) * 2;

    float acc[2][4][4];
    #pragma unroll
    for (int mt = 0; mt < 2; mt++)
        #pragma unroll
        for (int nt = 0; nt < 4; nt++)
            #pragma unroll
            for (int r = 0; r < 4; r++) acc[mt][nt][r] = 0.f;

    #pragma unroll
    for (int ks = 0; ks < 8; ks++) {
        int k0 = ks * 16;
        unsigned ah[2][4];
        #pragma unroll
        for (int mt = 0; mt < 2; mt++) {
            int r0 = wm * 32 + mt * 16 + g;
            ah[mt][0] = *(const unsigned*)(As_h + r0 * AROW + k0 + kk);
            ah[mt][1] = *(const unsigned*)(As_h + (r0 + 8) * AROW + k0 + kk);
            ah[mt][2] = *(const unsigned*)(As_h + r0 * AROW + k0 + kk + 8);
            ah[mt][3] = *(const unsigned*)(As_h + (r0 + 8) * AROW + k0 + kk + 8);
        }
        #pragma unroll
        for (int nt = 0; nt < 4; nt++) {
            int c = wn * 32 + nt * 8 + g;
            unsigned bh0 = *(const unsigned*)(Ws_h + c * AROW + k0 + kk);
            unsigned bh1 = *(const unsigned*)(Ws_h + c * AROW + k0 + kk + 8);
            #pragma unroll
            for (int mt = 0; mt < 2; mt++) {
                float* a = acc[mt][nt];
                mma_f16(a[0], a[1], a[2], a[3],
                        ah[mt][0], ah[mt][1], ah[mt][2], ah[mt][3], bh0, bh1);
            }
        }
    }

    // ---- epilogue: scale by dinv[row], store fp16
    #pragma unroll
    for (int mt = 0; mt < 2; mt++) {
        int r0 = m0 + wm * 32 + mt * 16 + g;
        int r1 = r0 + 8;
        float dv0 = (r0 < N) ? g_dinv[r0] : 0.f;
        float dv1 = (r1 < N) ? g_dinv[r1] : 0.f;
        #pragma unroll
        for (int nt = 0; nt < 4; nt++) {
            int col = wn * 32 + nt * 8 + (lane & 3) * 2;
            float* a = acc[mt][nt];
            if (r0 < N)
                *(__half2*)(g_hh + (size_t)r0 * D + col) =
                    __floats2half2_rn(a[0] * dv0, a[1] * dv0);
            if (r1 < N)
                *(__half2*)(g_hh + (size_t)r1 * D + col) =
                    __floats2half2_rn(a[2] * dv1, a[3] * dv1);
        }
    }
}

// ---------------------------------------------------------------- Aggregate
// out[i] = dinv[i] * (h_s[i] + sum_{e in row i} h_s[col[e]]) + b
// one warp per node (proven best); lane handles 4 halves (8B) of the row.
__device__ __forceinline__ void add_h4(float4& acc, uint2 v) {
    float2 a = __half22float2(*(__half2*)&v.x);
    float2 b = __half22float2(*(__half2*)&v.y);
    acc.x += a.x; acc.y += a.y; acc.z += b.x; acc.w += b.y;
}

template<typename OutT>
__global__ void __launch_bounds__(256) agg_kernel(
    const float* __restrict__ bias, OutT* __restrict__ out, int N,
    int zero_first)
{
    int w    = (int)((blockIdx.x * blockDim.x + threadIdx.x) >> 5);
    int lane = threadIdx.x & 31;
    if (w >= N) return;

    if (zero_first && w == 0) {   // final layer: out[0] = zeros
        if (sizeof(OutT) == 4)
            ((float4*)out)[lane] = make_float4(0.f, 0.f, 0.f, 0.f);
        else
            ((uint2*)out)[lane] = make_uint2(0u, 0u);
        return;
    }

    const uint2* H2 = (const uint2*)g_hh;   // 32 uint2 per row
    float4 acc = make_float4(0.f, 0.f, 0.f, 0.f);
    add_h4(acc, H2[(size_t)w * 32 + lane]); // self-loop term
    int beg = g_off[w], end = g_end[w];

    int e = beg;
    for (; e + 3 < end; e += 4) {
        int s0 = g_col[e],     s1 = g_col[e + 1];
        int s2 = g_col[e + 2], s3 = g_col[e + 3];
        uint2 v0 = H2[(size_t)s0 * 32 + lane];
        uint2 v1 = H2[(size_t)s1 * 32 + lane];
        uint2 v2 = H2[(size_t)s2 * 32 + lane];
        uint2 v3 = H2[(size_t)s3 * 32 + lane];
        add_h4(acc, v0); add_h4(acc, v1);
        add_h4(acc, v2); add_h4(acc, v3);
    }
    for (; e < end; e++) {
        uint2 v0 = H2[(size_t)g_col[e] * 32 + lane];
        add_h4(acc, v0);
    }

    float dv = g_dinv[w];
    float4 bb = ((const float4*)bias)[lane];
    float4 o;
    o.x = fmaf(acc.x, dv, bb.x);
    o.y = fmaf(acc.y, dv, bb.y);
    o.z = fmaf(acc.z, dv, bb.z);
    o.w = fmaf(acc.w, dv, bb.w);
    if (sizeof(OutT) == 4) {
        ((float4*)out)[(size_t)w * 32 + lane] = o;
    } else {
        uint2 p;
        *(__half2*)&p.x = __floats2half2_rn(o.x, o.y);
        *(__half2*)&p.y = __floats2half2_rn(o.z, o.w);
        ((uint2*)out)[(size_t)w * 32 + lane] = p;
    }
}

// ---------------------------------------------------------------- launch
// s2: wsplit (no deps, runs during CSR prefix) -> wait evOff -> gemm1.
// default: init -> count -> offsets -> [evOff] -> fill -> wait evJoin -> chain.
extern "C" void kernel_launch(void* const* d_in, const int* in_sizes, int n_in,
                              void* d_out, int out_size)
{
    const float* emb = (const float*)d_in[0];
    const float* W1  = (const float*)d_in[1];
    const float* b1  = (const float*)d_in[2];
    const float* W2  = (const float*)d_in[3];
    const float* b2  = (const float*)d_in[4];
    const float* W3  = (const float*)d_in[5];
    const float* b3  = (const float*)d_in[6];
    const void*  ei  = d_in[7];

    int N = in_sizes[0] / D;
    int E = in_sizes[7] / 2;
    float* out = (float*)d_out;

    void* p;
    cudaGetSymbolAddress(&p, g_xh);  __half* Xh = (__half*)p;

    static cudaStream_t s2 = nullptr;
    static cudaEvent_t evOff = nullptr, evJoin = nullptr;
    if (!s2) {
        cudaFuncSetAttribute(gemm_tc_kernel<0>,
            cudaFuncAttributeMaxDynamicSharedMemorySize, SM_TOT);
        cudaFuncSetAttribute(gemm_tc_kernel<1>,
            cudaFuncAttributeMaxDynamicSharedMemorySize, SM_TOT);
        cudaStreamCreateWithFlags(&s2, cudaStreamNonBlocking);
        cudaEventCreateWithFlags(&evOff, cudaEventDisableTiming);
        cudaEventCreateWithFlags(&evJoin, cudaEventDisableTiming);
    }

    int tb = 256;
    int nblk = (N + 255) / 256;
    int gemm_grid = (N + 63) / 64;
    int agg_grid  = (N + 7) / 8;

    // ---- s2: weight convert immediately (no dependencies)
    wsplit_kernel<<<(3 * D * D + tb - 1) / tb, tb, 0, s2>>>(W1, W2, W3);

    // ---- default: CSR prefix (produces g_dinv at offsets)
    init_kernel<<<nblk, 256>>>((const int*)ei, N);
    count_kernel<<<(E + tb - 1) / tb, tb>>>(ei, E);
    offsets_kernel<<<nblk, 256>>>(N);
    cudaEventRecord(evOff, 0);

    // ---- s2: layer-1 GEMM (reads g_dinv + g_Wht; NOT g_col)
    cudaStreamWaitEvent(s2, evOff, 0);
    gemm_tc_kernel<0><<<gemm_grid, 256, SM_TOT, s2>>>(emb, N, 0, 0);
    cudaEventRecord(evJoin, s2);

    // ---- default: fill CSR columns (concurrent with gemm1)
    fill_kernel<<<(E + tb - 1) / tb, tb>>>(ei, E);

    // ---- join, then the dependent chain
    cudaStreamWaitEvent(0, evJoin, 0);
    agg_kernel<__half><<<agg_grid, 256>>>(b1, Xh, N, 0);
    gemm_tc_kernel<1><<<gemm_grid, 256, SM_TOT>>>(Xh, N, 1, 1);
    agg_kernel<__half><<<agg_grid, 256>>>(b2, Xh, N, 0);
    gemm_tc_kernel<1><<<gemm_grid, 256, SM_TOT>>>(Xh, N, 1, 2);
    agg_kernel<float><<<agg_grid, 256>>>(b3, out, N, 1);
}